// round 16
// baseline (speedup 1.0000x reference)
#include <cuda_runtime.h>
#include <cuda_fp16.h>

// CustomLinearRNN via chunked parallel scan; all GEMM phases on mma.sync HMMA
// with fp16 hi/lo 3-term split (error ~2^-22).
//  k_pow  : P = A4^32, single CTA, 5 in-kernel squarings (HMMA)
//  k1     : UZ[t] = [A3;A1] x_t (HMMA, persistent grid 148)
//  k_rec(0): zero-state chunk scan -> g_W (HMMA)
//  k3     : boundary scan, P in regs, 4 threads/row + shfl (512 thr)
//  k_rec(1): rerun chunks from g_S -> out_hidden (HMMA)
//  k5     : known_t = Z_t + A2 h_{t-1} (HMMA, 256 thr, bt-split warps)

#define T_STEPS 4096
#define KDIM 64
#define HDIM 128
#define BDIM 128
#define CHUNK 32
#define NCHUNK 128
#define K1_GRID 148
#define SHS 136   // fp16 smem row stride (16B aligned, conflict-free)

typedef unsigned long long u64;
typedef unsigned int u32;

__device__ float g_UZ[(size_t)T_STEPS * 192 * BDIM];
__device__ float g_W[(size_t)NCHUNK * HDIM * BDIM];
__device__ float g_S[(size_t)NCHUNK * HDIM * BDIM];
__device__ float g_Pa[HDIM * HDIM];

// ---------- SIMT helpers ----------
__device__ __forceinline__ u64 ffma2(u64 a, u64 b, u64 c) {
    u64 d; asm("fma.rn.f32x2 %0, %1, %2, %3;" : "=l"(d) : "l"(a), "l"(b), "l"(c));
    return d;
}
__device__ __forceinline__ u64 fadd2(u64 a, u64 b) {
    u64 d; asm("add.rn.f32x2 %0, %1, %2;" : "=l"(d) : "l"(a), "l"(b));
    return d;
}
__device__ __forceinline__ void upk2(float& lo, float& hi, u64 u) {
    asm("mov.b64 {%0, %1}, %2;" : "=f"(lo), "=f"(hi) : "l"(u));
}

// ---------- mma helpers ----------
__device__ __forceinline__ u32 smem_u32(const void* p) {
    u32 a; asm("{ .reg .u64 t; cvta.to.shared.u64 t, %1; cvt.u32.u64 %0, t; }"
               : "=r"(a) : "l"(p));
    return a;
}
__device__ __forceinline__ void ldsmT(u32& r0, u32& r1, u32 addr) {
    asm volatile("ldmatrix.sync.aligned.m8n8.x2.trans.shared.b16 {%0,%1}, [%2];"
                 : "=r"(r0), "=r"(r1) : "r"(addr));
}
__device__ __forceinline__ void mma16816(float* d, const u32* a, u32 b0, u32 b1) {
    asm volatile("mma.sync.aligned.m16n8k16.row.col.f32.f16.f16.f32 "
        "{%0,%1,%2,%3}, {%4,%5,%6,%7}, {%8,%9}, {%0,%1,%2,%3};"
        : "+f"(d[0]), "+f"(d[1]), "+f"(d[2]), "+f"(d[3])
        : "r"(a[0]), "r"(a[1]), "r"(a[2]), "r"(a[3]), "r"(b0), "r"(b1));
}
__device__ __forceinline__ void sp2(float x, float y, u32& h, u32& l) {
    __half2 hh = __floats2half2_rn(x, y);
    float2 r = __half22float2(hh);
    __half2 ll = __floats2half2_rn(x - r.x, y - r.y);
    h = *(u32*)&hh; l = *(u32*)&ll;
}
__device__ __forceinline__ void loadA(const float* W, int n0, int lane,
                                      u32 ah[8][4], u32 al[8][4]) {
    const int r = lane >> 2, c = 2 * (lane & 3);
    #pragma unroll
    for (int ks = 0; ks < 8; ks++)
        #pragma unroll
        for (int q = 0; q < 4; q++) {
            const int rr = n0 + r + (q & 1) * 8;
            const int cc = 16 * ks + c + (q >> 1) * 8;
            const float2 p = *(const float2*)&W[rr * 128 + cc];
            sp2(p.x, p.y, ah[ks][q], al[ks][q]);
        }
}
__device__ __forceinline__ void stage(const float* src, __half* sHh, __half* sHl,
                                      int tid, int nthr) {
    for (int i = tid; i < HDIM * 64; i += nthr) {
        const int k = i >> 6, b2 = (i & 63) * 2;
        const float2 p = *(const float2*)&src[k * BDIM + b2];
        u32 h, l; sp2(p.x, p.y, h, l);
        *(u32*)&sHh[k * SHS + b2] = h;
        *(u32*)&sHl[k * SHS + b2] = l;
    }
}

// ---------------- k_pow: P = A4^32, single CTA, HMMA ----------------
__global__ __launch_bounds__(256, 1)
void k_pow(const float* __restrict__ A4)
{
    extern __shared__ __align__(16) __half sh[];
    __half* tiles = sh;
    const int tid = threadIdx.x;
    const int w = tid >> 5, lane = tid & 31;
    const int n0 = w * 16;
    const int r = lane >> 2, c = 2 * (lane & 3);

    stage(A4, tiles, tiles + HDIM * SHS, tid, 256);
    __syncthreads();

    #pragma unroll 1
    for (int iter = 0; iter < 5; iter++) {
        __half* curH = tiles + (iter & 1) * 2 * HDIM * SHS;
        __half* curL = curH + HDIM * SHS;
        __half* nxtH = tiles + ((iter + 1) & 1) * 2 * HDIM * SHS;
        __half* nxtL = nxtH + HDIM * SHS;

        u32 ah[8][4], al[8][4];
        #pragma unroll
        for (int ks = 0; ks < 8; ks++)
            #pragma unroll
            for (int q = 0; q < 4; q++) {
                const int rr = n0 + r + (q & 1) * 8;
                const int cc = 16 * ks + c + (q >> 1) * 8;
                const u32 ph = *(u32*)&curH[rr * SHS + cc];
                const u32 pl = *(u32*)&curL[rr * SHS + cc];
                const float2 fh = __half22float2(*(__half2*)&ph);
                const float2 fl = __half22float2(*(__half2*)&pl);
                sp2(fh.x + fl.x, fh.y + fl.y, ah[ks][q], al[ks][q]);
            }

        const u32 bH = smem_u32(curH), bL = smem_u32(curL);
        float d[16][4];
        #pragma unroll
        for (int bt = 0; bt < 16; bt++)
            d[bt][0] = d[bt][1] = d[bt][2] = d[bt][3] = 0.f;

        #pragma unroll
        for (int ks = 0; ks < 8; ks++) {
            const u32 ad = (u32)((16 * ks + (lane & 15)) * SHS) * 2;
            #pragma unroll
            for (int bt = 0; bt < 16; bt++) {
                u32 bh0, bh1, bl0, bl1;
                ldsmT(bh0, bh1, bH + ad + 16 * bt);
                ldsmT(bl0, bl1, bL + ad + 16 * bt);
                mma16816(d[bt], ah[ks], bh0, bh1);
                mma16816(d[bt], ah[ks], bl0, bl1);
                mma16816(d[bt], al[ks], bh0, bh1);
            }
        }
        __syncthreads();
        #pragma unroll
        for (int bt = 0; bt < 16; bt++) {
            u32 h0, l0, h1, l1;
            sp2(d[bt][0], d[bt][1], h0, l0);
            sp2(d[bt][2], d[bt][3], h1, l1);
            *(u32*)&nxtH[(n0 + r) * SHS + 8 * bt + c]     = h0;
            *(u32*)&nxtL[(n0 + r) * SHS + 8 * bt + c]     = l0;
            *(u32*)&nxtH[(n0 + r + 8) * SHS + 8 * bt + c] = h1;
            *(u32*)&nxtL[(n0 + r + 8) * SHS + 8 * bt + c] = l1;
            if (iter == 4) {
                *(float2*)&g_Pa[(n0 + r) * HDIM + 8 * bt + c]     = make_float2(d[bt][0], d[bt][1]);
                *(float2*)&g_Pa[(n0 + r + 8) * HDIM + 8 * bt + c] = make_float2(d[bt][2], d[bt][3]);
            }
        }
        __syncthreads();
    }
}

// ---------------- k1: UZ = [A3;A1] x_t (HMMA, persistent) ----------------
__global__ __launch_bounds__(384, 1)
void k1_ux(const float* __restrict__ x,
           const float* __restrict__ A3,
           const float* __restrict__ A1)
{
    extern __shared__ __align__(16) __half sh[];
    const int tid = threadIdx.x;
    const int w = tid >> 5, lane = tid & 31;
    const int n0 = w * 16;
    const int r = lane >> 2, c = 2 * (lane & 3);

    u32 ah[4][4], al[4][4];
    #pragma unroll
    for (int ks = 0; ks < 4; ks++)
        #pragma unroll
        for (int q = 0; q < 4; q++) {
            const int rr = n0 + r + (q & 1) * 8;
            const int cc = 16 * ks + c + (q >> 1) * 8;
            const float2 p = (rr < HDIM)
                ? *(const float2*)&A3[rr * KDIM + cc]
                : *(const float2*)&A1[(rr - HDIM) * KDIM + cc];
            sp2(p.x, p.y, ah[ks][q], al[ks][q]);
        }

    {
        const float* src = x + (size_t)blockIdx.x * KDIM * BDIM;
        for (int i = tid; i < KDIM * 64; i += 384) {
            const int k = i >> 6, b2 = (i & 63) * 2;
            const float2 p = *(const float2*)&src[k * BDIM + b2];
            u32 h, l; sp2(p.x, p.y, h, l);
            *(u32*)&sh[k * SHS + b2]              = h;
            *(u32*)&sh[KDIM * SHS + k * SHS + b2] = l;
        }
    }

    int buf = 0;
    #pragma unroll 1
    for (int t = blockIdx.x; t < T_STEPS; t += K1_GRID, buf ^= 1) {
        __syncthreads();
        const int tn = t + K1_GRID;
        if (tn < T_STEPS) {
            const float* src = x + (size_t)tn * KDIM * BDIM;
            __half* dH = sh + (buf ^ 1) * 2 * KDIM * SHS;
            __half* dL = dH + KDIM * SHS;
            for (int i = tid; i < KDIM * 64; i += 384) {
                const int k = i >> 6, b2 = (i & 63) * 2;
                const float2 p = *(const float2*)&src[k * BDIM + b2];
                u32 h, l; sp2(p.x, p.y, h, l);
                *(u32*)&dH[k * SHS + b2] = h;
                *(u32*)&dL[k * SHS + b2] = l;
            }
        }

        const u32 bH = smem_u32(sh + buf * 2 * KDIM * SHS);
        const u32 bL = bH + KDIM * SHS * 2;

        float d[16][4];
        #pragma unroll
        for (int bt = 0; bt < 16; bt++)
            d[bt][0] = d[bt][1] = d[bt][2] = d[bt][3] = 0.f;

        #pragma unroll
        for (int ks = 0; ks < 4; ks++) {
            const u32 ad = (u32)((16 * ks + (lane & 15)) * SHS) * 2;
            #pragma unroll
            for (int bt = 0; bt < 16; bt++) {
                u32 bh0, bh1, bl0, bl1;
                ldsmT(bh0, bh1, bH + ad + 16 * bt);
                ldsmT(bl0, bl1, bL + ad + 16 * bt);
                mma16816(d[bt], ah[ks], bh0, bh1);
                mma16816(d[bt], ah[ks], bl0, bl1);
                mma16816(d[bt], al[ks], bh0, bh1);
            }
        }
        float* go = g_UZ + (size_t)t * 192 * BDIM;
        #pragma unroll
        for (int bt = 0; bt < 16; bt++) {
            *(float2*)&go[(n0 + r) * BDIM + 8 * bt + c]     = make_float2(d[bt][0], d[bt][1]);
            *(float2*)&go[(n0 + r + 8) * BDIM + 8 * bt + c] = make_float2(d[bt][2], d[bt][3]);
        }
    }
}

// ---------------- k3: boundary scan, 4 threads/row + shfl ----------------
__global__ __launch_bounds__(512, 1)
void k3_scan(const float* __restrict__ h0)
{
    __shared__ __align__(16) float sS[2][128];
    const int b   = blockIdx.x;
    const int tid = threadIdx.x;
    const int row = tid >> 2;        // output row
    const int q   = tid & 3;         // dot quarter (32 elems)

    // P slice in registers: P[row][q*32 .. q*32+31]
    u64 pr[16];
    {
        const u64* prow = (const u64*)(g_Pa + row * HDIM + q * 32);
        #pragma unroll
        for (int m = 0; m < 16; m++) pr[m] = prow[m];
    }

    float s = h0[row * BDIM + b];
    if (q == 0) sS[0][row] = s;
    __syncthreads();

    const float* wp = g_W + (size_t)row * BDIM + b;
    float w = (q == 0) ? wp[0] : 0.f;

    #pragma unroll 1
    for (int i = 0; i < NCHUNK; i++) {
        if (q == 0) g_S[((size_t)i * HDIM + row) * BDIM + b] = s;
        const float wn = (q == 0 && i + 1 < NCHUNK)
                         ? wp[(size_t)(i + 1) * HDIM * BDIM] : 0.f;

        // partial dot over this thread's 32-element slice
        const ulonglong2* s2 = (const ulonglong2*)&sS[i & 1][q * 32];
        u64 a0 = 0ull, a1 = 0ull, a2 = 0ull, a3 = 0ull;
        #pragma unroll
        for (int m = 0; m < 8; m += 2) {
            const ulonglong2 q0 = s2[m];
            const ulonglong2 q1 = s2[m + 1];
            a0 = ffma2(pr[2 * m],     q0.x, a0);
            a1 = ffma2(pr[2 * m + 1], q0.y, a1);
            a2 = ffma2(pr[2 * m + 2], q1.x, a2);
            a3 = ffma2(pr[2 * m + 3], q1.y, a3);
        }
        const u64 aa = fadd2(fadd2(a0, a1), fadd2(a2, a3));
        float lo, hi; upk2(lo, hi, aa);
        float part = lo + hi;
        // combine 4 quarters (lanes differ in bits 0-1)
        part += __shfl_xor_sync(0xffffffffu, part, 1);
        part += __shfl_xor_sync(0xffffffffu, part, 2);

        s = part + w;
        if (q == 0) sS[(i + 1) & 1][row] = s;
        __syncthreads();
        w = wn;
    }
}

// ---------------- k_rec: HMMA chunk recurrence ----------------
__global__ __launch_bounds__(256, 1)
void k_rec(const int mode, const float* __restrict__ A4w,
           float* __restrict__ out_hidden)
{
    extern __shared__ __align__(16) __half sh[];
    __half* sHh = sh;
    __half* sHl = sh + HDIM * SHS;

    const int ic  = blockIdx.x;
    const int tid = threadIdx.x;
    const int w = tid >> 5, lane = tid & 31;
    const int n0 = w * 16;
    const int r = lane >> 2, c = 2 * (lane & 3);

    u32 ah[8][4], al[8][4];
    loadA(A4w, n0, lane, ah, al);

    stage(mode ? g_S + (size_t)ic * HDIM * BDIM
               : g_UZ + (size_t)(ic * CHUNK) * 192 * BDIM,
          sHh, sHl, tid, 256);
    __syncthreads();

    const u32 bH = smem_u32(sHh), bL = smem_u32(sHl);

    #pragma unroll 1
    for (int cc = (mode ? 0 : 1); cc < CHUNK; cc++) {
        const int t = ic * CHUNK + cc;

        float d[16][4];
        const float* u = g_UZ + (size_t)t * 192 * BDIM;
        #pragma unroll
        for (int bt = 0; bt < 16; bt++) {
            const float2 p0 = *(const float2*)&u[(n0 + r) * BDIM + 8 * bt + c];
            const float2 p1 = *(const float2*)&u[(n0 + r + 8) * BDIM + 8 * bt + c];
            d[bt][0] = p0.x; d[bt][1] = p0.y; d[bt][2] = p1.x; d[bt][3] = p1.y;
        }

        #pragma unroll
        for (int ks = 0; ks < 8; ks++) {
            const u32 ad = (u32)((16 * ks + (lane & 15)) * SHS) * 2;
            #pragma unroll
            for (int bt = 0; bt < 16; bt++) {
                u32 bh0, bh1, bl0, bl1;
                ldsmT(bh0, bh1, bH + ad + 16 * bt);
                ldsmT(bl0, bl1, bL + ad + 16 * bt);
                mma16816(d[bt], ah[ks], bh0, bh1);
                mma16816(d[bt], ah[ks], bl0, bl1);
                mma16816(d[bt], al[ks], bh0, bh1);
            }
        }
        __syncthreads();

        const bool wr = mode || (cc == CHUNK - 1);
        float* go = mode ? out_hidden + (size_t)t * HDIM * BDIM
                         : g_W + (size_t)ic * HDIM * BDIM;
        #pragma unroll
        for (int bt = 0; bt < 16; bt++) {
            if (cc < CHUNK - 1) {
                u32 h0, l0, h1, l1;
                sp2(d[bt][0], d[bt][1], h0, l0);
                sp2(d[bt][2], d[bt][3], h1, l1);
                *(u32*)&sHh[(n0 + r) * SHS + 8 * bt + c]     = h0;
                *(u32*)&sHl[(n0 + r) * SHS + 8 * bt + c]     = l0;
                *(u32*)&sHh[(n0 + r + 8) * SHS + 8 * bt + c] = h1;
                *(u32*)&sHl[(n0 + r + 8) * SHS + 8 * bt + c] = l1;
            }
            if (wr) {
                *(float2*)&go[(n0 + r) * BDIM + 8 * bt + c]     = make_float2(d[bt][0], d[bt][1]);
                *(float2*)&go[(n0 + r + 8) * BDIM + 8 * bt + c] = make_float2(d[bt][2], d[bt][3]);
            }
        }
        __syncthreads();
    }
}

// ---------------- k5: known_t = Z_t + A2 h_{t-1} (256 thr, bt-split) ----------------
__global__ __launch_bounds__(256, 1)
void k5_known(const float* __restrict__ A2w,
              const float* __restrict__ out_hidden,
              float* __restrict__ out_known)
{
    extern __shared__ __align__(16) __half sh[];
    __half* sHh = sh;
    __half* sHl = sh + HDIM * SHS;

    const int t   = blockIdx.x;
    const int tid = threadIdx.x;
    const int w = tid >> 5, lane = tid & 31;
    const int wq = w & 3;        // row group (16 rows of known)
    const int half = w >> 2;     // bt half: 0 -> bt 0..7, 1 -> bt 8..15
    const int n0 = wq * 16;
    const int r = lane >> 2, c = 2 * (lane & 3);

    u32 ah[8][4], al[8][4];
    loadA(A2w, n0, lane, ah, al);

    const float* hsrc = (t % CHUNK == 0)
        ? g_S + (size_t)(t / CHUNK) * HDIM * BDIM
        : out_hidden + (size_t)(t - 1) * HDIM * BDIM;
    stage(hsrc, sHh, sHl, tid, 256);
    __syncthreads();

    const u32 bH = smem_u32(sHh), bL = smem_u32(sHl);

    float d[8][4];
    const float* z = g_UZ + ((size_t)t * 192 + 128) * BDIM;
    #pragma unroll
    for (int bt = 0; bt < 8; bt++) {
        const int btx = bt + half * 8;
        const float2 p0 = *(const float2*)&z[(n0 + r) * BDIM + 8 * btx + c];
        const float2 p1 = *(const float2*)&z[(n0 + r + 8) * BDIM + 8 * btx + c];
        d[bt][0] = p0.x; d[bt][1] = p0.y; d[bt][2] = p1.x; d[bt][3] = p1.y;
    }
    #pragma unroll
    for (int ks = 0; ks < 8; ks++) {
        const u32 ad = (u32)((16 * ks + (lane & 15)) * SHS) * 2;
        #pragma unroll
        for (int bt = 0; bt < 8; bt++) {
            const int btx = bt + half * 8;
            u32 bh0, bh1, bl0, bl1;
            ldsmT(bh0, bh1, bH + ad + 16 * btx);
            ldsmT(bl0, bl1, bL + ad + 16 * btx);
            mma16816(d[bt], ah[ks], bh0, bh1);
            mma16816(d[bt], ah[ks], bl0, bl1);
            mma16816(d[bt], al[ks], bh0, bh1);
        }
    }
    float* go = out_known + (size_t)t * KDIM * BDIM;
    #pragma unroll
    for (int bt = 0; bt < 8; bt++) {
        const int btx = bt + half * 8;
        *(float2*)&go[(n0 + r) * BDIM + 8 * btx + c]     = make_float2(d[bt][0], d[bt][1]);
        *(float2*)&go[(n0 + r + 8) * BDIM + 8 * btx + c] = make_float2(d[bt][2], d[bt][3]);
    }
}

// ---------------- host ----------------
extern "C" void kernel_launch(void* const* d_in, const int* in_sizes, int n_in,
                              void* d_out, int out_size)
{
    const float* x  = (const float*)d_in[0];
    const float* h0 = (const float*)d_in[1];
    const float* A1 = (const float*)d_in[2];
    const float* A2 = (const float*)d_in[3];
    const float* A3 = (const float*)d_in[4];
    const float* A4 = (const float*)d_in[5];

    float* out_known  = (float*)d_out;
    float* out_hidden = (float*)d_out + (size_t)T_STEPS * KDIM * BDIM;

    const int smemP = 2 * 2 * HDIM * SHS * 2;   // 139264 (k_pow)
    const int smem1 = 2 * 2 * KDIM * SHS * 2;   // 69632  (k1)
    const int smemR = 2 * HDIM * SHS * 2;       // 69632  (k_rec, k5)

    cudaFuncSetAttribute(k_pow,   cudaFuncAttributeMaxDynamicSharedMemorySize, smemP);
    cudaFuncSetAttribute(k1_ux,   cudaFuncAttributeMaxDynamicSharedMemorySize, smem1);
    cudaFuncSetAttribute(k_rec,   cudaFuncAttributeMaxDynamicSharedMemorySize, smemR);
    cudaFuncSetAttribute(k5_known,cudaFuncAttributeMaxDynamicSharedMemorySize, smemR);

    k_pow<<<1, 256, smemP>>>(A4);
    k1_ux<<<K1_GRID, 384, smem1>>>(x, A3, A1);
    k_rec<<<NCHUNK, 256, smemR>>>(0, A4, nullptr);
    k3_scan<<<BDIM, 512>>>(h0);
    k_rec<<<NCHUNK, 256, smemR>>>(1, A4, out_hidden);
    k5_known<<<T_STEPS, 256, smemR>>>(A2, out_hidden, out_known);

    (void)in_sizes; (void)n_in; (void)out_size;
}

// round 17
// speedup vs baseline: 1.6365x; 1.6365x over previous
#include <cuda_runtime.h>
#include <cuda_fp16.h>

// CustomLinearRNN via chunked parallel scan; all GEMM phases on mma.sync HMMA
// with fp16 hi/lo 3-term split (error ~2^-22).
//  k_pow  : A4^2..A4^64 by squaring (g_Pa=A4^32, g_Pb=A4^64), single CTA
//  k1     : UZ[t] = [A3;A1] x_t (HMMA, persistent grid 148)
//  k_rec(0): zero-state chunk scan -> g_W (HMMA)
//  k_gemm1 (fold):   W2[j] = P32*W[2j] + W[2j+1]          (64 CTAs, parallel)
//  k3     : boundary scan over 64 folded steps with P64, P in regs
//  k_gemm1 (unfold): s[2j+1] = P32*s[2j] + W[2j]          (64 CTAs, parallel)
//  k_rec(1): rerun chunks from g_S -> out_hidden (HMMA)
//  k5     : known_t = Z_t + A2 h_{t-1} (HMMA, parallel over t)

#define T_STEPS 4096
#define KDIM 64
#define HDIM 128
#define BDIM 128
#define CHUNK 32
#define NCHUNK 128
#define K1_GRID 148
#define SHS 136   // fp16 smem row stride (16B aligned, conflict-free)
#define PLANE (HDIM * BDIM)   // 16384 floats

typedef unsigned long long u64;
typedef unsigned int u32;

__device__ float g_UZ[(size_t)T_STEPS * 192 * BDIM];
__device__ float g_W[(size_t)NCHUNK * PLANE];
__device__ float g_W2[(size_t)(NCHUNK / 2) * PLANE];
__device__ float g_S[(size_t)NCHUNK * PLANE];
__device__ float g_Pa[HDIM * HDIM];   // A4^32
__device__ float g_Pb[HDIM * HDIM];   // A4^64

// ---------- SIMT helpers ----------
__device__ __forceinline__ u64 ffma2(u64 a, u64 b, u64 c) {
    u64 d; asm("fma.rn.f32x2 %0, %1, %2, %3;" : "=l"(d) : "l"(a), "l"(b), "l"(c));
    return d;
}
__device__ __forceinline__ u64 fadd2(u64 a, u64 b) {
    u64 d; asm("add.rn.f32x2 %0, %1, %2;" : "=l"(d) : "l"(a), "l"(b));
    return d;
}
__device__ __forceinline__ void upk2(float& lo, float& hi, u64 u) {
    asm("mov.b64 {%0, %1}, %2;" : "=f"(lo), "=f"(hi) : "l"(u));
}

// ---------- mma helpers ----------
__device__ __forceinline__ u32 smem_u32(const void* p) {
    u32 a; asm("{ .reg .u64 t; cvta.to.shared.u64 t, %1; cvt.u32.u64 %0, t; }"
               : "=r"(a) : "l"(p));
    return a;
}
__device__ __forceinline__ void ldsmT(u32& r0, u32& r1, u32 addr) {
    asm volatile("ldmatrix.sync.aligned.m8n8.x2.trans.shared.b16 {%0,%1}, [%2];"
                 : "=r"(r0), "=r"(r1) : "r"(addr));
}
__device__ __forceinline__ void mma16816(float* d, const u32* a, u32 b0, u32 b1) {
    asm volatile("mma.sync.aligned.m16n8k16.row.col.f32.f16.f16.f32 "
        "{%0,%1,%2,%3}, {%4,%5,%6,%7}, {%8,%9}, {%0,%1,%2,%3};"
        : "+f"(d[0]), "+f"(d[1]), "+f"(d[2]), "+f"(d[3])
        : "r"(a[0]), "r"(a[1]), "r"(a[2]), "r"(a[3]), "r"(b0), "r"(b1));
}
__device__ __forceinline__ void sp2(float x, float y, u32& h, u32& l) {
    __half2 hh = __floats2half2_rn(x, y);
    float2 r = __half22float2(hh);
    __half2 ll = __floats2half2_rn(x - r.x, y - r.y);
    h = *(u32*)&hh; l = *(u32*)&ll;
}
__device__ __forceinline__ void loadA(const float* W, int n0, int lane,
                                      u32 ah[8][4], u32 al[8][4]) {
    const int r = lane >> 2, c = 2 * (lane & 3);
    #pragma unroll
    for (int ks = 0; ks < 8; ks++)
        #pragma unroll
        for (int q = 0; q < 4; q++) {
            const int rr = n0 + r + (q & 1) * 8;
            const int cc = 16 * ks + c + (q >> 1) * 8;
            const float2 p = *(const float2*)&W[rr * 128 + cc];
            sp2(p.x, p.y, ah[ks][q], al[ks][q]);
        }
}
__device__ __forceinline__ void stage(const float* src, __half* sHh, __half* sHl,
                                      int tid, int nthr) {
    for (int i = tid; i < HDIM * 64; i += nthr) {
        const int k = i >> 6, b2 = (i & 63) * 2;
        const float2 p = *(const float2*)&src[k * BDIM + b2];
        u32 h, l; sp2(p.x, p.y, h, l);
        *(u32*)&sHh[k * SHS + b2] = h;
        *(u32*)&sHl[k * SHS + b2] = l;
    }
}

// ---------------- k_pow: A4^2..A4^64, single CTA, HMMA ----------------
__global__ __launch_bounds__(256, 1)
void k_pow(const float* __restrict__ A4)
{
    extern __shared__ __align__(16) __half sh[];
    __half* tiles = sh;
    const int tid = threadIdx.x;
    const int w = tid >> 5, lane = tid & 31;
    const int n0 = w * 16;
    const int r = lane >> 2, c = 2 * (lane & 3);

    stage(A4, tiles, tiles + HDIM * SHS, tid, 256);
    __syncthreads();

    #pragma unroll 1
    for (int iter = 0; iter < 6; iter++) {
        __half* curH = tiles + (iter & 1) * 2 * HDIM * SHS;
        __half* curL = curH + HDIM * SHS;
        __half* nxtH = tiles + ((iter + 1) & 1) * 2 * HDIM * SHS;
        __half* nxtL = nxtH + HDIM * SHS;

        u32 ah[8][4], al[8][4];
        #pragma unroll
        for (int ks = 0; ks < 8; ks++)
            #pragma unroll
            for (int q = 0; q < 4; q++) {
                const int rr = n0 + r + (q & 1) * 8;
                const int cc = 16 * ks + c + (q >> 1) * 8;
                const u32 ph = *(u32*)&curH[rr * SHS + cc];
                const u32 pl = *(u32*)&curL[rr * SHS + cc];
                const float2 fh = __half22float2(*(__half2*)&ph);
                const float2 fl = __half22float2(*(__half2*)&pl);
                sp2(fh.x + fl.x, fh.y + fl.y, ah[ks][q], al[ks][q]);
            }

        const u32 bH = smem_u32(curH), bL = smem_u32(curL);
        float d[16][4];
        #pragma unroll
        for (int bt = 0; bt < 16; bt++)
            d[bt][0] = d[bt][1] = d[bt][2] = d[bt][3] = 0.f;

        #pragma unroll
        for (int ks = 0; ks < 8; ks++) {
            const u32 ad = (u32)((16 * ks + (lane & 15)) * SHS) * 2;
            #pragma unroll
            for (int bt = 0; bt < 16; bt++) {
                u32 bh0, bh1, bl0, bl1;
                ldsmT(bh0, bh1, bH + ad + 16 * bt);
                ldsmT(bl0, bl1, bL + ad + 16 * bt);
                mma16816(d[bt], ah[ks], bh0, bh1);
                mma16816(d[bt], ah[ks], bl0, bl1);
                mma16816(d[bt], al[ks], bh0, bh1);
            }
        }
        __syncthreads();
        #pragma unroll
        for (int bt = 0; bt < 16; bt++) {
            u32 h0, l0, h1, l1;
            sp2(d[bt][0], d[bt][1], h0, l0);
            sp2(d[bt][2], d[bt][3], h1, l1);
            *(u32*)&nxtH[(n0 + r) * SHS + 8 * bt + c]     = h0;
            *(u32*)&nxtL[(n0 + r) * SHS + 8 * bt + c]     = l0;
            *(u32*)&nxtH[(n0 + r + 8) * SHS + 8 * bt + c] = h1;
            *(u32*)&nxtL[(n0 + r + 8) * SHS + 8 * bt + c] = l1;
            if (iter >= 4) {
                float* dst = (iter == 4) ? g_Pa : g_Pb;
                *(float2*)&dst[(n0 + r) * HDIM + 8 * bt + c]     = make_float2(d[bt][0], d[bt][1]);
                *(float2*)&dst[(n0 + r + 8) * HDIM + 8 * bt + c] = make_float2(d[bt][2], d[bt][3]);
            }
        }
        __syncthreads();
    }
}

// ---------------- k1: UZ = [A3;A1] x_t (HMMA, persistent) ----------------
__global__ __launch_bounds__(384, 1)
void k1_ux(const float* __restrict__ x,
           const float* __restrict__ A3,
           const float* __restrict__ A1)
{
    extern __shared__ __align__(16) __half sh[];
    const int tid = threadIdx.x;
    const int w = tid >> 5, lane = tid & 31;
    const int n0 = w * 16;
    const int r = lane >> 2, c = 2 * (lane & 3);

    u32 ah[4][4], al[4][4];
    #pragma unroll
    for (int ks = 0; ks < 4; ks++)
        #pragma unroll
        for (int q = 0; q < 4; q++) {
            const int rr = n0 + r + (q & 1) * 8;
            const int cc = 16 * ks + c + (q >> 1) * 8;
            const float2 p = (rr < HDIM)
                ? *(const float2*)&A3[rr * KDIM + cc]
                : *(const float2*)&A1[(rr - HDIM) * KDIM + cc];
            sp2(p.x, p.y, ah[ks][q], al[ks][q]);
        }

    {
        const float* src = x + (size_t)blockIdx.x * KDIM * BDIM;
        for (int i = tid; i < KDIM * 64; i += 384) {
            const int k = i >> 6, b2 = (i & 63) * 2;
            const float2 p = *(const float2*)&src[k * BDIM + b2];
            u32 h, l; sp2(p.x, p.y, h, l);
            *(u32*)&sh[k * SHS + b2]              = h;
            *(u32*)&sh[KDIM * SHS + k * SHS + b2] = l;
        }
    }

    int buf = 0;
    #pragma unroll 1
    for (int t = blockIdx.x; t < T_STEPS; t += K1_GRID, buf ^= 1) {
        __syncthreads();
        const int tn = t + K1_GRID;
        if (tn < T_STEPS) {
            const float* src = x + (size_t)tn * KDIM * BDIM;
            __half* dH = sh + (buf ^ 1) * 2 * KDIM * SHS;
            __half* dL = dH + KDIM * SHS;
            for (int i = tid; i < KDIM * 64; i += 384) {
                const int k = i >> 6, b2 = (i & 63) * 2;
                const float2 p = *(const float2*)&src[k * BDIM + b2];
                u32 h, l; sp2(p.x, p.y, h, l);
                *(u32*)&dH[k * SHS + b2] = h;
                *(u32*)&dL[k * SHS + b2] = l;
            }
        }

        const u32 bH = smem_u32(sh + buf * 2 * KDIM * SHS);
        const u32 bL = bH + KDIM * SHS * 2;

        float d[16][4];
        #pragma unroll
        for (int bt = 0; bt < 16; bt++)
            d[bt][0] = d[bt][1] = d[bt][2] = d[bt][3] = 0.f;

        #pragma unroll
        for (int ks = 0; ks < 4; ks++) {
            const u32 ad = (u32)((16 * ks + (lane & 15)) * SHS) * 2;
            #pragma unroll
            for (int bt = 0; bt < 16; bt++) {
                u32 bh0, bh1, bl0, bl1;
                ldsmT(bh0, bh1, bH + ad + 16 * bt);
                ldsmT(bl0, bl1, bL + ad + 16 * bt);
                mma16816(d[bt], ah[ks], bh0, bh1);
                mma16816(d[bt], ah[ks], bl0, bl1);
                mma16816(d[bt], al[ks], bh0, bh1);
            }
        }
        float* go = g_UZ + (size_t)t * 192 * BDIM;
        #pragma unroll
        for (int bt = 0; bt < 16; bt++) {
            *(float2*)&go[(n0 + r) * BDIM + 8 * bt + c]     = make_float2(d[bt][0], d[bt][1]);
            *(float2*)&go[(n0 + r + 8) * BDIM + 8 * bt + c] = make_float2(d[bt][2], d[bt][3]);
        }
    }
}

// ---------------- k_gemm1: D[j] = split_mma(Aw, B[j]) + C[j] (one step) ----------------
__global__ __launch_bounds__(256, 1)
void k_gemm1(const float* __restrict__ Aw,
             const float* __restrict__ Bbase, size_t bStride,
             const float* __restrict__ Cbase, size_t cStride,
             float* __restrict__ Dbase, size_t dStride)
{
    extern __shared__ __align__(16) __half sh[];
    __half* sHh = sh;
    __half* sHl = sh + HDIM * SHS;

    const int j   = blockIdx.x;
    const int tid = threadIdx.x;
    const int w = tid >> 5, lane = tid & 31;
    const int n0 = w * 16;
    const int r = lane >> 2, c = 2 * (lane & 3);

    u32 ah[8][4], al[8][4];
    loadA(Aw, n0, lane, ah, al);

    stage(Bbase + (size_t)j * bStride, sHh, sHl, tid, 256);
    __syncthreads();

    const u32 bH = smem_u32(sHh), bL = smem_u32(sHl);

    float d[16][4];
    const float* cs = Cbase + (size_t)j * cStride;
    #pragma unroll
    for (int bt = 0; bt < 16; bt++) {
        const float2 p0 = *(const float2*)&cs[(n0 + r) * BDIM + 8 * bt + c];
        const float2 p1 = *(const float2*)&cs[(n0 + r + 8) * BDIM + 8 * bt + c];
        d[bt][0] = p0.x; d[bt][1] = p0.y; d[bt][2] = p1.x; d[bt][3] = p1.y;
    }
    #pragma unroll
    for (int ks = 0; ks < 8; ks++) {
        const u32 ad = (u32)((16 * ks + (lane & 15)) * SHS) * 2;
        #pragma unroll
        for (int bt = 0; bt < 16; bt++) {
            u32 bh0, bh1, bl0, bl1;
            ldsmT(bh0, bh1, bH + ad + 16 * bt);
            ldsmT(bl0, bl1, bL + ad + 16 * bt);
            mma16816(d[bt], ah[ks], bh0, bh1);
            mma16816(d[bt], ah[ks], bl0, bl1);
            mma16816(d[bt], al[ks], bh0, bh1);
        }
    }
    float* go = Dbase + (size_t)j * dStride;
    #pragma unroll
    for (int bt = 0; bt < 16; bt++) {
        *(float2*)&go[(n0 + r) * BDIM + 8 * bt + c]     = make_float2(d[bt][0], d[bt][1]);
        *(float2*)&go[(n0 + r + 8) * BDIM + 8 * bt + c] = make_float2(d[bt][2], d[bt][3]);
    }
}

// ---------------- k3: folded boundary scan (64 steps, P64 in regs) ----------------
__global__ __launch_bounds__(128, 1)
void k3_scan(const float* __restrict__ h0)
{
    __shared__ __align__(16) float sS[2][128];
    const int b   = blockIdx.x;
    const int tid = threadIdx.x;   // = output row

    // P64 row in registers
    u64 pr[64];
    {
        const u64* prow = (const u64*)(g_Pb + tid * HDIM);
        #pragma unroll
        for (int m = 0; m < 64; m++) pr[m] = prow[m];
    }

    float s = h0[tid * BDIM + b];
    sS[0][tid] = s;
    __syncthreads();

    const float* wp = g_W2 + (size_t)tid * BDIM + b;
    float w = wp[0];

    #pragma unroll 1
    for (int i = 0; i < NCHUNK / 2; i++) {
        g_S[((size_t)(2 * i) * HDIM + tid) * BDIM + b] = s;
        const float wn = (i + 1 < NCHUNK / 2) ? wp[(size_t)(i + 1) * PLANE] : 0.f;

        const ulonglong2* s2 = (const ulonglong2*)&sS[i & 1][0];
        u64 a0 = 0ull, a1 = 0ull, a2 = 0ull, a3 = 0ull;
        #pragma unroll
        for (int m = 0; m < 32; m += 2) {
            const ulonglong2 q0 = s2[m];
            const ulonglong2 q1 = s2[m + 1];
            a0 = ffma2(pr[2 * m],     q0.x, a0);
            a1 = ffma2(pr[2 * m + 1], q0.y, a1);
            a2 = ffma2(pr[2 * m + 2], q1.x, a2);
            a3 = ffma2(pr[2 * m + 3], q1.y, a3);
        }
        const u64 aa = fadd2(fadd2(a0, a1), fadd2(a2, a3));
        float lo, hi; upk2(lo, hi, aa);
        s = lo + hi + w;
        sS[(i + 1) & 1][tid] = s;
        __syncthreads();
        w = wn;
    }
}

// ---------------- k_rec: HMMA chunk recurrence ----------------
__global__ __launch_bounds__(256, 1)
void k_rec(const int mode, const float* __restrict__ A4w,
           float* __restrict__ out_hidden)
{
    extern __shared__ __align__(16) __half sh[];
    __half* sHh = sh;
    __half* sHl = sh + HDIM * SHS;

    const int ic  = blockIdx.x;
    const int tid = threadIdx.x;
    const int w = tid >> 5, lane = tid & 31;
    const int n0 = w * 16;
    const int r = lane >> 2, c = 2 * (lane & 3);

    u32 ah[8][4], al[8][4];
    loadA(A4w, n0, lane, ah, al);

    stage(mode ? g_S + (size_t)ic * PLANE
               : g_UZ + (size_t)(ic * CHUNK) * 192 * BDIM,
          sHh, sHl, tid, 256);
    __syncthreads();

    const u32 bH = smem_u32(sHh), bL = smem_u32(sHl);

    #pragma unroll 1
    for (int cc = (mode ? 0 : 1); cc < CHUNK; cc++) {
        const int t = ic * CHUNK + cc;

        float d[16][4];
        const float* u = g_UZ + (size_t)t * 192 * BDIM;
        #pragma unroll
        for (int bt = 0; bt < 16; bt++) {
            const float2 p0 = *(const float2*)&u[(n0 + r) * BDIM + 8 * bt + c];
            const float2 p1 = *(const float2*)&u[(n0 + r + 8) * BDIM + 8 * bt + c];
            d[bt][0] = p0.x; d[bt][1] = p0.y; d[bt][2] = p1.x; d[bt][3] = p1.y;
        }

        #pragma unroll
        for (int ks = 0; ks < 8; ks++) {
            const u32 ad = (u32)((16 * ks + (lane & 15)) * SHS) * 2;
            #pragma unroll
            for (int bt = 0; bt < 16; bt++) {
                u32 bh0, bh1, bl0, bl1;
                ldsmT(bh0, bh1, bH + ad + 16 * bt);
                ldsmT(bl0, bl1, bL + ad + 16 * bt);
                mma16816(d[bt], ah[ks], bh0, bh1);
                mma16816(d[bt], ah[ks], bl0, bl1);
                mma16816(d[bt], al[ks], bh0, bh1);
            }
        }
        __syncthreads();

        const bool wr = mode || (cc == CHUNK - 1);
        float* go = mode ? out_hidden + (size_t)t * HDIM * BDIM
                         : g_W + (size_t)ic * PLANE;
        #pragma unroll
        for (int bt = 0; bt < 16; bt++) {
            if (cc < CHUNK - 1) {
                u32 h0, l0, h1, l1;
                sp2(d[bt][0], d[bt][1], h0, l0);
                sp2(d[bt][2], d[bt][3], h1, l1);
                *(u32*)&sHh[(n0 + r) * SHS + 8 * bt + c]     = h0;
                *(u32*)&sHl[(n0 + r) * SHS + 8 * bt + c]     = l0;
                *(u32*)&sHh[(n0 + r + 8) * SHS + 8 * bt + c] = h1;
                *(u32*)&sHl[(n0 + r + 8) * SHS + 8 * bt + c] = l1;
            }
            if (wr) {
                *(float2*)&go[(n0 + r) * BDIM + 8 * bt + c]     = make_float2(d[bt][0], d[bt][1]);
                *(float2*)&go[(n0 + r + 8) * BDIM + 8 * bt + c] = make_float2(d[bt][2], d[bt][3]);
            }
        }
        __syncthreads();
    }
}

// ---------------- k5: known_t = Z_t + A2 h_{t-1} (128 thr, R14 version) ----------------
__global__ __launch_bounds__(128, 1)
void k5_known(const float* __restrict__ A2w,
              const float* __restrict__ out_hidden,
              float* __restrict__ out_known)
{
    extern __shared__ __align__(16) __half sh[];
    __half* sHh = sh;
    __half* sHl = sh + HDIM * SHS;

    const int t   = blockIdx.x;
    const int tid = threadIdx.x;
    const int w = tid >> 5, lane = tid & 31;
    const int n0 = w * 16;
    const int r = lane >> 2, c = 2 * (lane & 3);

    u32 ah[8][4], al[8][4];
    loadA(A2w, n0, lane, ah, al);

    const float* hsrc = (t % CHUNK == 0)
        ? g_S + (size_t)(t / CHUNK) * PLANE
        : out_hidden + (size_t)(t - 1) * HDIM * BDIM;
    stage(hsrc, sHh, sHl, tid, 128);
    __syncthreads();

    const u32 bH = smem_u32(sHh), bL = smem_u32(sHl);

    float d[16][4];
    const float* z = g_UZ + ((size_t)t * 192 + 128) * BDIM;
    #pragma unroll
    for (int bt = 0; bt < 16; bt++) {
        const float2 p0 = *(const float2*)&z[(n0 + r) * BDIM + 8 * bt + c];
        const float2 p1 = *(const float2*)&z[(n0 + r + 8) * BDIM + 8 * bt + c];
        d[bt][0] = p0.x; d[bt][1] = p0.y; d[bt][2] = p1.x; d[bt][3] = p1.y;
    }
    #pragma unroll
    for (int ks = 0; ks < 8; ks++) {
        const u32 ad = (u32)((16 * ks + (lane & 15)) * SHS) * 2;
        #pragma unroll
        for (int bt = 0; bt < 16; bt++) {
            u32 bh0, bh1, bl0, bl1;
            ldsmT(bh0, bh1, bH + ad + 16 * bt);
            ldsmT(bl0, bl1, bL + ad + 16 * bt);
            mma16816(d[bt], ah[ks], bh0, bh1);
            mma16816(d[bt], ah[ks], bl0, bl1);
            mma16816(d[bt], al[ks], bh0, bh1);
        }
    }
    float* go = out_known + (size_t)t * KDIM * BDIM;
    #pragma unroll
    for (int bt = 0; bt < 16; bt++) {
        *(float2*)&go[(n0 + r) * BDIM + 8 * bt + c]     = make_float2(d[bt][0], d[bt][1]);
        *(float2*)&go[(n0 + r + 8) * BDIM + 8 * bt + c] = make_float2(d[bt][2], d[bt][3]);
    }
}

// ---------------- host ----------------
extern "C" void kernel_launch(void* const* d_in, const int* in_sizes, int n_in,
                              void* d_out, int out_size)
{
    const float* x  = (const float*)d_in[0];
    const float* h0 = (const float*)d_in[1];
    const float* A1 = (const float*)d_in[2];
    const float* A2 = (const float*)d_in[3];
    const float* A3 = (const float*)d_in[4];
    const float* A4 = (const float*)d_in[5];

    float* out_known  = (float*)d_out;
    float* out_hidden = (float*)d_out + (size_t)T_STEPS * KDIM * BDIM;

    const int smemP = 2 * 2 * HDIM * SHS * 2;   // 139264 (k_pow)
    const int smem1 = 2 * 2 * KDIM * SHS * 2;   // 69632  (k1)
    const int smemR = 2 * HDIM * SHS * 2;       // 69632  (k_rec, k5, k_gemm1)

    cudaFuncSetAttribute(k_pow,   cudaFuncAttributeMaxDynamicSharedMemorySize, smemP);
    cudaFuncSetAttribute(k1_ux,   cudaFuncAttributeMaxDynamicSharedMemorySize, smem1);
    cudaFuncSetAttribute(k_rec,   cudaFuncAttributeMaxDynamicSharedMemorySize, smemR);
    cudaFuncSetAttribute(k5_known,cudaFuncAttributeMaxDynamicSharedMemorySize, smemR);
    cudaFuncSetAttribute(k_gemm1, cudaFuncAttributeMaxDynamicSharedMemorySize, smemR);

    float *pa, *pw, *pw2, *ps;
    cudaGetSymbolAddress((void**)&pa,  g_Pa);
    cudaGetSymbolAddress((void**)&pw,  g_W);
    cudaGetSymbolAddress((void**)&pw2, g_W2);
    cudaGetSymbolAddress((void**)&ps,  g_S);

    k_pow<<<1, 256, smemP>>>(A4);
    k1_ux<<<K1_GRID, 384, smem1>>>(x, A3, A1);
    k_rec<<<NCHUNK, 256, smemR>>>(0, A4, nullptr);
    // fold: W2[j] = P32*W[2j] + W[2j+1]
    k_gemm1<<<NCHUNK / 2, 256, smemR>>>(pa, pw, (size_t)2 * PLANE,
                                        pw + PLANE, (size_t)2 * PLANE,
                                        pw2, (size_t)PLANE);
    k3_scan<<<BDIM, 128>>>(h0);
    // unfold: s[2j+1] = P32*s[2j] + W[2j]
    k_gemm1<<<NCHUNK / 2, 256, smemR>>>(pa, ps, (size_t)2 * PLANE,
                                        pw, (size_t)2 * PLANE,
                                        ps + PLANE, (size_t)2 * PLANE);
    k_rec<<<NCHUNK, 256, smemR>>>(1, A4, out_hidden);
    k5_known<<<T_STEPS, 128, smemR>>>(A2, out_hidden, out_known);

    (void)in_sizes; (void)n_in; (void)out_size;
}